// round 6
// baseline (speedup 1.0000x reference)
#include <cuda_runtime.h>
#include <math.h>

#define NTOK 2048
#define DIM  512
#define NEXP 16
#define TOPK 2
#define HIDD 2048
#define NASSIGN (NTOK*TOPK)

// ---------------- scratch (device globals: no allocation allowed) ----------
__device__ float g_xn[NTOK*DIM];          // 4 MB  normalized activations
__device__ float g_H [NASSIGN*HIDD];      // 32 MB silu(h) per assignment row
__device__ float g_Y [NASSIGN*DIM];       // 8 MB  expert outputs per assignment row
__device__ int   g_cnt[NEXP];
__device__ int   g_off[NEXP+1];
__device__ int   g_tok[NEXP*NTOK];        // per-expert token lists
__device__ float g_gate[NTOK*TOPK];
__device__ int   g_se[NTOK*TOPK];         // expert id per (token,k)
__device__ int   g_sp[NTOK*TOPK];         // position within expert list per (token,k)

// ---- packed f32x2 FMA (Blackwell FFMA2; only reachable via PTX) -----------
__device__ __forceinline__ unsigned long long ffma2(
        unsigned long long a, unsigned long long b, unsigned long long c) {
    unsigned long long d;
    asm("fma.rn.f32x2 %0, %1, %2, %3;" : "=l"(d) : "l"(a), "l"(b), "l"(c));
    return d;
}
__device__ __forceinline__ unsigned long long pack2(float lo, float hi) {
    unsigned long long r;
    asm("mov.b64 %0, {%1, %2};" : "=l"(r) : "f"(lo), "f"(hi));
    return r;
}
__device__ __forceinline__ void unpack2(unsigned long long v, float& lo, float& hi) {
    asm("mov.b64 {%0, %1}, %2;" : "=f"(lo), "=f"(hi) : "l"(v));
}

// ---------------------------------------------------------------------------
__global__ void zero_cnt_kernel() {
    if (threadIdx.x < NEXP) g_cnt[threadIdx.x] = 0;
}

// one block (512 threads) per token
__global__ __launch_bounds__(512)
void router_kernel(const float* __restrict__ x, const float* __restrict__ wn,
                   const float* __restrict__ Wr, const float* __restrict__ br) {
    __shared__ float WrS[DIM*NEXP];   // 32 KB
    __shared__ float s_red[16];
    __shared__ float s_pe[16*16];
    __shared__ float s_logit[16];
    __shared__ float s_rinv;

    const int n = blockIdx.x;
    const int d = threadIdx.x;
    const int wid = d >> 5, lane = d & 31;

    // stage Wr [D,E] row-major into smem (coalesced float4)
    {
        float4* ws = (float4*)&WrS[d*16];
        const float4* wg = (const float4*)(Wr + d*16);
        ws[0] = wg[0]; ws[1] = wg[1]; ws[2] = wg[2]; ws[3] = wg[3];
    }

    const float xv = x[n*DIM + d];
    // sum of squares, fixed-order tree reduce
    float s = xv * xv;
    #pragma unroll
    for (int o = 16; o > 0; o >>= 1) s += __shfl_down_sync(0xffffffffu, s, o);
    if (lane == 0) s_red[wid] = s;
    __syncthreads();
    if (d == 0) {
        float t = 0.f;
        #pragma unroll
        for (int w = 0; w < 16; w++) t += s_red[w];
        s_rinv = rsqrtf(t / (float)DIM + 1e-10f);
    }
    __syncthreads();

    const float xnv = wn[d] * xv * s_rinv;
    g_xn[n*DIM + d] = xnv;

    // logits: 16 dot products of length 512, deterministic shfl reduction
    #pragma unroll
    for (int e = 0; e < NEXP; e++) {
        float p = xnv * WrS[d*16 + e];
        #pragma unroll
        for (int o = 16; o > 0; o >>= 1) p += __shfl_down_sync(0xffffffffu, p, o);
        if (lane == 0) s_pe[wid*16 + e] = p;
    }
    __syncthreads();
    if (d < NEXP) {
        float l = br[d];
        #pragma unroll
        for (int w = 0; w < 16; w++) l += s_pe[w*16 + d];
        s_logit[d] = l;
    }
    __syncthreads();

    if (d == 0) {
        // top-2 with jax tie-break (first occurrence wins via strict >)
        int i0 = 0; float b0 = s_logit[0];
        #pragma unroll
        for (int e = 1; e < NEXP; e++) if (s_logit[e] > b0) { b0 = s_logit[e]; i0 = e; }
        int i1 = -1; float b1 = -1e30f;
        #pragma unroll
        for (int e = 0; e < NEXP; e++) {
            if (e == i0) continue;
            if (s_logit[e] > b1) { b1 = s_logit[e]; i1 = e; }
        }
        const float z  = expf(b1 - b0);
        const float w0 = 1.f / (1.f + z);
        const float w1 = z   / (1.f + z);
        const int p0 = atomicAdd(&g_cnt[i0], 1);
        const int p1 = atomicAdd(&g_cnt[i1], 1);
        g_tok[i0*NTOK + p0] = n;
        g_tok[i1*NTOK + p1] = n;
        g_gate[n*2+0] = w0;  g_gate[n*2+1] = w1;
        g_se[n*2+0]   = i0;  g_se[n*2+1]   = i1;
        g_sp[n*2+0]   = p0;  g_sp[n*2+1]   = p1;
    }
}

__global__ void offsets_kernel() {
    if (threadIdx.x == 0) {
        int s = 0;
        #pragma unroll
        for (int e = 0; e < NEXP; e++) { g_off[e] = s; s += g_cnt[e]; }
        g_off[NEXP] = s;
    }
}

// ---------------------------------------------------------------------------
// Double-buffered tiled fp32 GEMM with FFMA2 microkernel.
// BM=BN=128, BK=16, 256 threads, 8x8 microtile (stored as 8x4 f32x2 pairs).
// FIRST=1: H[off+m] = silu(gather(xn)@W1[e] + b1[e])   (K=512,  LDB=HIDD)
// FIRST=0: Y[off+m] =        H        @W2[e] + b2[e]   (K=2048, LDB=DIM)
template<int FIRST>
__global__ __launch_bounds__(256, 2)
void ffn_gemm_kernel(const float* __restrict__ W, const float* __restrict__ bias) {
    const int e  = blockIdx.z;
    const int ne = g_cnt[e];
    const int m0 = blockIdx.x * 128;
    if (m0 >= ne) return;
    const int n0  = blockIdx.y * 128;
    const int off = g_off[e];
    const int tid = threadIdx.x;
    const int tx  = tid & 15, ty = tid >> 4;

    constexpr int K   = FIRST ? DIM  : HIDD;
    constexpr int LDB = FIRST ? HIDD : DIM;
    const float* Bp = W + (size_t)e * K * LDB + n0;

    __shared__ float As[2][16][128];
    __shared__ float Bs[2][16][128];

    // A row pointers (2 passes x 64 rows)
    const float* arp[2];
    #pragma unroll
    for (int p = 0; p < 2; p++) {
        const int m = m0 + p*64 + (tid >> 2);
        const float* ap = nullptr;
        if (m < ne) {
            if (FIRST) ap = g_xn + (size_t)g_tok[e*NTOK + m] * DIM;
            else       ap = g_H  + (size_t)(off + m) * HIDD;
        }
        arp[p] = ap;
    }
    const int ac4 = (tid & 3) * 4;          // A: k-offset within tile
    const int ar  = tid >> 2;               // A: row within 64-row pass
    const int br_ = tid >> 5;               // B: row within 8-row pass
    const int bc4 = (tid & 31) * 4;         // B: col

    // 8x8 fp32 accumulators as 8x4 packed f32x2 (pairs along j)
    unsigned long long acc2[8][4];
    #pragma unroll
    for (int i = 0; i < 8; i++)
        #pragma unroll
        for (int j = 0; j < 4; j++) acc2[i][j] = 0ull;   // (0.f, 0.f)

    // ---- load tile 0 into buffer 0 ----
    #pragma unroll
    for (int p = 0; p < 2; p++) {
        float4 v = make_float4(0.f, 0.f, 0.f, 0.f);
        if (arp[p]) v = *(const float4*)(arp[p] + ac4);
        const int r = p*64 + ar;
        As[0][ac4+0][r] = v.x; As[0][ac4+1][r] = v.y;
        As[0][ac4+2][r] = v.z; As[0][ac4+3][r] = v.w;
    }
    #pragma unroll
    for (int p = 0; p < 2; p++) {
        const int r = p*8 + br_;
        *(float4*)&Bs[0][r][bc4] = *(const float4*)(Bp + (size_t)r * LDB + bc4);
    }
    __syncthreads();

    int cur = 0;
    for (int k0 = 0; k0 < K; k0 += 16) {
        const bool has_next = (k0 + 16 < K);

        // ---- prefetch next tile into registers ----
        float4 av[2], bv[2];
        if (has_next) {
            #pragma unroll
            for (int p = 0; p < 2; p++) {
                av[p] = make_float4(0.f, 0.f, 0.f, 0.f);
                if (arp[p]) av[p] = *(const float4*)(arp[p] + k0 + 16 + ac4);
            }
            #pragma unroll
            for (int p = 0; p < 2; p++) {
                const int r = p*8 + br_;
                bv[p] = *(const float4*)(Bp + (size_t)(k0 + 16 + r) * LDB + bc4);
            }
        }

        // ---- compute on current buffer (FFMA2 microkernel) ----
        #pragma unroll
        for (int kk = 0; kk < 16; kk++) {
            float a[8];
            *(float4*)&a[0] = *(const float4*)&As[cur][kk][ty*8];
            *(float4*)&a[4] = *(const float4*)&As[cur][kk][ty*8 + 4];
            // b as 4 packed f32x2 (16B-aligned smem rows -> safe reinterpret)
            union { float4 f; unsigned long long u[2]; } bu0, bu1;
            bu0.f = *(const float4*)&Bs[cur][kk][tx*8];
            bu1.f = *(const float4*)&Bs[cur][kk][tx*8 + 4];
            const unsigned long long b2[4] = { bu0.u[0], bu0.u[1], bu1.u[0], bu1.u[1] };
            #pragma unroll
            for (int i = 0; i < 8; i++) {
                const unsigned long long a2 = pack2(a[i], a[i]);
                #pragma unroll
                for (int j = 0; j < 4; j++)
                    acc2[i][j] = ffma2(a2, b2[j], acc2[i][j]);
            }
        }

        // ---- store prefetched regs into the other buffer ----
        if (has_next) {
            const int nxt = cur ^ 1;
            #pragma unroll
            for (int p = 0; p < 2; p++) {
                const int r = p*64 + ar;
                As[nxt][ac4+0][r] = av[p].x; As[nxt][ac4+1][r] = av[p].y;
                As[nxt][ac4+2][r] = av[p].z; As[nxt][ac4+3][r] = av[p].w;
            }
            #pragma unroll
            for (int p = 0; p < 2; p++) {
                const int r = p*8 + br_;
                *(float4*)&Bs[nxt][r][bc4] = bv[p];
            }
            __syncthreads();
            cur = nxt;
        }
    }

    const float* bp = bias + (size_t)e * LDB + n0 + tx*8;
    #pragma unroll
    for (int i = 0; i < 8; i++) {
        const int m = m0 + ty*8 + i;
        if (m >= ne) continue;
        float* orow;
        if (FIRST) orow = g_H + (size_t)(off + m) * HIDD + n0 + tx*8;
        else       orow = g_Y + (size_t)(off + m) * DIM  + n0 + tx*8;
        #pragma unroll
        for (int j = 0; j < 4; j++) {
            float lo, hi;
            unpack2(acc2[i][j], lo, hi);
            float v0 = lo + bp[2*j+0];
            float v1 = hi + bp[2*j+1];
            if (FIRST) {
                v0 = v0 / (1.f + expf(-v0));   // silu
                v1 = v1 / (1.f + expf(-v1));
            }
            orow[2*j+0] = v0;
            orow[2*j+1] = v1;
        }
    }
}

// out = x + g0*Y[row0] + g1*Y[row1]   (fixed k order -> deterministic)
__global__ void combine_kernel(const float* __restrict__ x, float* __restrict__ out) {
    const int idx = blockIdx.x * blockDim.x + threadIdx.x;
    if (idx >= NTOK*DIM) return;
    const int n = idx / DIM, d = idx % DIM;
    const int r0 = g_off[g_se[n*2+0]] + g_sp[n*2+0];
    const int r1 = g_off[g_se[n*2+1]] + g_sp[n*2+1];
    out[idx] = x[idx]
             + g_gate[n*2+0] * g_Y[(size_t)r0*DIM + d]
             + g_gate[n*2+1] * g_Y[(size_t)r1*DIM + d];
}

// ---------------------------------------------------------------------------
extern "C" void kernel_launch(void* const* d_in, const int* in_sizes, int n_in,
                              void* d_out, int out_size) {
    const float* x  = (const float*)d_in[0];
    const float* wn = (const float*)d_in[1];
    const float* Wr = (const float*)d_in[2];
    const float* br = (const float*)d_in[3];
    const float* W1 = (const float*)d_in[4];
    const float* b1 = (const float*)d_in[5];
    const float* W2 = (const float*)d_in[6];
    const float* b2 = (const float*)d_in[7];
    float* out = (float*)d_out;

    zero_cnt_kernel<<<1, 32>>>();
    router_kernel<<<NTOK, 512>>>(x, wn, Wr, br);
    offsets_kernel<<<1, 32>>>();
    ffn_gemm_kernel<1><<<dim3(16, HIDD/128, NEXP), 256>>>(W1, b1);
    ffn_gemm_kernel<0><<<dim3(16, DIM /128, NEXP), 256>>>(W2, b2);
    combine_kernel<<<(NTOK*DIM + 255)/256, 256>>>(x, out);
}

// round 10
// speedup vs baseline: 1.7199x; 1.7199x over previous
#include <cuda_runtime.h>
#include <math.h>
#include <stdint.h>

#define NTOK 2048
#define DIM  512
#define NEXP 16
#define TOPK 2
#define HIDD 2048
#define NASSIGN (NTOK*TOPK)

// ---------------- scratch (device globals: no allocation allowed) ----------
__device__ float g_xn[NTOK*DIM];          // 4 MB  normalized activations
__device__ float g_H [NASSIGN*HIDD];      // 32 MB silu(h) per assignment row
__device__ float g_Y [NASSIGN*DIM];       // 8 MB  expert outputs per assignment row
__device__ int   g_cnt[NEXP];
__device__ int   g_off[NEXP+1];
__device__ int   g_tok[NEXP*NTOK];        // per-expert token lists
__device__ float g_gate[NTOK*TOPK];
__device__ int   g_se[NTOK*TOPK];         // expert id per (token,k)
__device__ int   g_sp[NTOK*TOPK];         // position within expert list per (token,k)

// ---- tf32 helpers ---------------------------------------------------------
__device__ __forceinline__ uint32_t f2tf(float f) {
    uint32_t r;
    asm("cvt.rna.tf32.f32 %0, %1;" : "=r"(r) : "f"(f));
    return r;
}
__device__ __forceinline__ void mma_tf32(float* c, const uint32_t* a, const uint32_t* b) {
    asm("mma.sync.aligned.m16n8k8.row.col.f32.tf32.tf32.f32 "
        "{%0,%1,%2,%3}, {%4,%5,%6,%7}, {%8,%9}, {%0,%1,%2,%3};"
        : "+f"(c[0]), "+f"(c[1]), "+f"(c[2]), "+f"(c[3])
        : "r"(a[0]), "r"(a[1]), "r"(a[2]), "r"(a[3]), "r"(b[0]), "r"(b[1]));
}

// ---------------------------------------------------------------------------
__global__ void zero_cnt_kernel() {
    if (threadIdx.x < NEXP) g_cnt[threadIdx.x] = 0;
}

// one block (512 threads) per token
__global__ __launch_bounds__(512)
void router_kernel(const float* __restrict__ x, const float* __restrict__ wn,
                   const float* __restrict__ Wr, const float* __restrict__ br) {
    __shared__ float WrS[DIM*NEXP];   // 32 KB
    __shared__ float s_red[16];
    __shared__ float s_pe[16*16];
    __shared__ float s_logit[16];
    __shared__ float s_rinv;

    const int n = blockIdx.x;
    const int d = threadIdx.x;
    const int wid = d >> 5, lane = d & 31;

    // stage Wr [D,E] row-major into smem (coalesced float4)
    {
        float4* ws = (float4*)&WrS[d*16];
        const float4* wg = (const float4*)(Wr + d*16);
        ws[0] = wg[0]; ws[1] = wg[1]; ws[2] = wg[2]; ws[3] = wg[3];
    }

    const float xv = x[n*DIM + d];
    // sum of squares, fixed-order tree reduce
    float s = xv * xv;
    #pragma unroll
    for (int o = 16; o > 0; o >>= 1) s += __shfl_down_sync(0xffffffffu, s, o);
    if (lane == 0) s_red[wid] = s;
    __syncthreads();
    if (d == 0) {
        float t = 0.f;
        #pragma unroll
        for (int w = 0; w < 16; w++) t += s_red[w];
        s_rinv = rsqrtf(t / (float)DIM + 1e-10f);
    }
    __syncthreads();

    const float xnv = wn[d] * xv * s_rinv;
    g_xn[n*DIM + d] = xnv;

    // logits: 16 dot products of length 512, deterministic shfl reduction
    #pragma unroll
    for (int e = 0; e < NEXP; e++) {
        float p = xnv * WrS[d*16 + e];
        #pragma unroll
        for (int o = 16; o > 0; o >>= 1) p += __shfl_down_sync(0xffffffffu, p, o);
        if (lane == 0) s_pe[wid*16 + e] = p;
    }
    __syncthreads();
    if (d < NEXP) {
        float l = br[d];
        #pragma unroll
        for (int w = 0; w < 16; w++) l += s_pe[w*16 + d];
        s_logit[d] = l;
    }
    __syncthreads();

    if (d == 0) {
        // top-2 with jax tie-break (first occurrence wins via strict >)
        int i0 = 0; float b0 = s_logit[0];
        #pragma unroll
        for (int e = 1; e < NEXP; e++) if (s_logit[e] > b0) { b0 = s_logit[e]; i0 = e; }
        int i1 = -1; float b1 = -1e30f;
        #pragma unroll
        for (int e = 0; e < NEXP; e++) {
            if (e == i0) continue;
            if (s_logit[e] > b1) { b1 = s_logit[e]; i1 = e; }
        }
        const float z  = expf(b1 - b0);
        const float w0 = 1.f / (1.f + z);
        const float w1 = z   / (1.f + z);
        const int p0 = atomicAdd(&g_cnt[i0], 1);
        const int p1 = atomicAdd(&g_cnt[i1], 1);
        g_tok[i0*NTOK + p0] = n;
        g_tok[i1*NTOK + p1] = n;
        g_gate[n*2+0] = w0;  g_gate[n*2+1] = w1;
        g_se[n*2+0]   = i0;  g_se[n*2+1]   = i1;
        g_sp[n*2+0]   = p0;  g_sp[n*2+1]   = p1;
    }
}

__global__ void offsets_kernel() {
    if (threadIdx.x == 0) {
        int s = 0;
        #pragma unroll
        for (int e = 0; e < NEXP; e++) { g_off[e] = s; s += g_cnt[e]; }
        g_off[NEXP] = s;
    }
}

// ---------------------------------------------------------------------------
// TF32 mma.sync GEMM. BM=128, BN=64, BK=16, 256 threads (8 warps, 4x2).
// Warp tile 32x32 = 2 m16 x 4 n8 mma tiles, k in chunks of 8.
// Smem strides padded for conflict-free fragment loads:
//   As[128][20] (g*20+t distinct mod 32), Bs[16][72] (t*72+g -> t*8+g distinct).
// FIRST=1: H[off+m] = silu(gather(xn)@W1[e] + b1[e])   (K=512,  LDB=HIDD)
// FIRST=0: Y[off+m] =        H        @W2[e] + b2[e]   (K=2048, LDB=DIM)
template<int FIRST>
__global__ __launch_bounds__(256, 2)
void ffn_mma_kernel(const float* __restrict__ W, const float* __restrict__ bias) {
    const int e  = blockIdx.z;
    const int ne = g_cnt[e];
    const int m0 = blockIdx.x * 128;
    if (m0 >= ne) return;
    const int n0  = blockIdx.y * 64;
    const int off = g_off[e];
    const int tid  = threadIdx.x;
    const int lane = tid & 31, warp = tid >> 5;
    const int g = lane >> 2, t = lane & 3;
    const int wm = warp & 3, wn = warp >> 2;

    constexpr int K   = FIRST ? DIM  : HIDD;
    constexpr int LDB = FIRST ? HIDD : DIM;
    const float* Bp = W + (size_t)e * K * LDB + n0;

    __shared__ __align__(16) uint32_t As[2][128][20];
    __shared__ __align__(16) uint32_t Bs[2][16][72];

    // A loader mapping: 2 passes x 64 rows; thread -> row ar, col ac..ac+3
    const int ar = tid >> 2;            // 0..63
    const int ac = (tid & 3) * 4;       // 0,4,8,12
    const float* arp[2];
    #pragma unroll
    for (int p = 0; p < 2; p++) {
        const int m = m0 + p*64 + ar;
        const float* ap = nullptr;
        if (m < ne) {
            if (FIRST) ap = g_xn + (size_t)g_tok[e*NTOK + m] * DIM;
            else       ap = g_H  + (size_t)(off + m) * HIDD;
        }
        arp[p] = ap;
    }
    // B loader mapping: thread -> row brow (0..15), col bcol..bcol+3
    const int brow = tid >> 4;
    const int bcol = (tid & 15) * 4;

    float acc[2][4][4];
    #pragma unroll
    for (int mt = 0; mt < 2; mt++)
        #pragma unroll
        for (int nt = 0; nt < 4; nt++)
            #pragma unroll
            for (int i = 0; i < 4; i++) acc[mt][nt][i] = 0.f;

    // ---- load tile 0 ----
    #pragma unroll
    for (int p = 0; p < 2; p++) {
        float4 v = make_float4(0.f, 0.f, 0.f, 0.f);
        if (arp[p]) v = *(const float4*)(arp[p] + ac);
        uint4 u = make_uint4(f2tf(v.x), f2tf(v.y), f2tf(v.z), f2tf(v.w));
        *(uint4*)&As[0][p*64 + ar][ac] = u;
    }
    {
        float4 v = *(const float4*)(Bp + (size_t)brow * LDB + bcol);
        uint4 u = make_uint4(f2tf(v.x), f2tf(v.y), f2tf(v.z), f2tf(v.w));
        *(uint4*)&Bs[0][brow][bcol] = u;
    }
    __syncthreads();

    int cur = 0;
    for (int k0 = 0; k0 < K; k0 += 16) {
        const bool has_next = (k0 + 16 < K);

        // ---- prefetch next tile into registers ----
        float4 av[2], bv;
        if (has_next) {
            #pragma unroll
            for (int p = 0; p < 2; p++) {
                av[p] = make_float4(0.f, 0.f, 0.f, 0.f);
                if (arp[p]) av[p] = *(const float4*)(arp[p] + k0 + 16 + ac);
            }
            bv = *(const float4*)(Bp + (size_t)(k0 + 16 + brow) * LDB + bcol);
        }

        // ---- compute on current buffer: 2 k8-chunks ----
        #pragma unroll
        for (int kk0 = 0; kk0 < 16; kk0 += 8) {
            uint32_t a[2][4];
            #pragma unroll
            for (int mt = 0; mt < 2; mt++) {
                const int row = wm*32 + mt*16 + g;
                a[mt][0] = As[cur][row  ][kk0 + t];
                a[mt][1] = As[cur][row+8][kk0 + t];
                a[mt][2] = As[cur][row  ][kk0 + t + 4];
                a[mt][3] = As[cur][row+8][kk0 + t + 4];
            }
            uint32_t b[4][2];
            #pragma unroll
            for (int nt = 0; nt < 4; nt++) {
                const int col = wn*32 + nt*8 + g;
                b[nt][0] = Bs[cur][kk0 + t    ][col];
                b[nt][1] = Bs[cur][kk0 + t + 4][col];
            }
            #pragma unroll
            for (int mt = 0; mt < 2; mt++)
                #pragma unroll
                for (int nt = 0; nt < 4; nt++)
                    mma_tf32(acc[mt][nt], a[mt], b[nt]);
        }

        // ---- store prefetched tile to the other buffer ----
        if (has_next) {
            const int nxt = cur ^ 1;
            #pragma unroll
            for (int p = 0; p < 2; p++) {
                uint4 u = make_uint4(f2tf(av[p].x), f2tf(av[p].y),
                                     f2tf(av[p].z), f2tf(av[p].w));
                *(uint4*)&As[nxt][p*64 + ar][ac] = u;
            }
            {
                uint4 u = make_uint4(f2tf(bv.x), f2tf(bv.y), f2tf(bv.z), f2tf(bv.w));
                *(uint4*)&Bs[nxt][brow][bcol] = u;
            }
            __syncthreads();
            cur = nxt;
        }
    }

    // ---- epilogue: bias (+silu), write ----
    const float* bpr = bias + (size_t)e * LDB + n0;
    #pragma unroll
    for (int mt = 0; mt < 2; mt++) {
        #pragma unroll
        for (int r = 0; r < 2; r++) {
            const int m = m0 + wm*32 + mt*16 + g + r*8;
            if (m >= ne) continue;
            float* orow = (FIRST ? g_H + (size_t)(off + m) * HIDD
                                 : g_Y + (size_t)(off + m) * DIM) + n0;
            #pragma unroll
            for (int nt = 0; nt < 4; nt++) {
                const int lc = wn*32 + nt*8 + 2*t;
                float v0 = acc[mt][nt][r*2+0] + bpr[lc];
                float v1 = acc[mt][nt][r*2+1] + bpr[lc+1];
                if (FIRST) {
                    v0 = v0 / (1.f + expf(-v0));   // silu
                    v1 = v1 / (1.f + expf(-v1));
                }
                *(float2*)(orow + lc) = make_float2(v0, v1);
            }
        }
    }
}

// out = x + g0*Y[row0] + g1*Y[row1]   (fixed k order -> deterministic)
__global__ void combine_kernel(const float* __restrict__ x, float* __restrict__ out) {
    const int idx = blockIdx.x * blockDim.x + threadIdx.x;
    if (idx >= NTOK*DIM) return;
    const int n = idx / DIM, d = idx % DIM;
    const int r0 = g_off[g_se[n*2+0]] + g_sp[n*2+0];
    const int r1 = g_off[g_se[n*2+1]] + g_sp[n*2+1];
    out[idx] = x[idx]
             + g_gate[n*2+0] * g_Y[(size_t)r0*DIM + d]
             + g_gate[n*2+1] * g_Y[(size_t)r1*DIM + d];
}

// ---------------------------------------------------------------------------
extern "C" void kernel_launch(void* const* d_in, const int* in_sizes, int n_in,
                              void* d_out, int out_size) {
    const float* x  = (const float*)d_in[0];
    const float* wn = (const float*)d_in[1];
    const float* Wr = (const float*)d_in[2];
    const float* br = (const float*)d_in[3];
    const float* W1 = (const float*)d_in[4];
    const float* b1 = (const float*)d_in[5];
    const float* W2 = (const float*)d_in[6];
    const float* b2 = (const float*)d_in[7];
    float* out = (float*)d_out;

    zero_cnt_kernel<<<1, 32>>>();
    router_kernel<<<NTOK, 512>>>(x, wn, Wr, br);
    offsets_kernel<<<1, 32>>>();
    ffn_mma_kernel<1><<<dim3(16, HIDD/64, NEXP), 256>>>(W1, b1);
    ffn_mma_kernel<0><<<dim3(16, DIM /64, NEXP), 256>>>(W2, b2);
    combine_kernel<<<(NTOK*DIM + 255)/256, 256>>>(x, out);
}

// round 11
// speedup vs baseline: 2.5865x; 1.5039x over previous
#include <cuda_runtime.h>
#include <math.h>
#include <stdint.h>

#define NTOK 2048
#define DIM  512
#define NEXP 16
#define TOPK 2
#define HIDD 2048
#define NASSIGN (NTOK*TOPK)

// ---------------- scratch (device globals: no allocation allowed) ----------
__device__ float g_xn[NTOK*DIM];          // 4 MB  normalized activations
__device__ float g_H [NASSIGN*HIDD];      // 32 MB silu(h) per assignment row
__device__ float g_Y [NASSIGN*DIM];       // 8 MB  expert outputs per assignment row
__device__ int   g_cnt[NEXP];
__device__ int   g_off[NEXP+1];
__device__ int   g_tok[NEXP*NTOK];        // per-expert token lists
__device__ float g_gate[NTOK*TOPK];
__device__ int   g_se[NTOK*TOPK];         // expert id per (token,k)
__device__ int   g_sp[NTOK*TOPK];         // position within expert list per (token,k)

// ---- helpers --------------------------------------------------------------
__device__ __forceinline__ void mma_tf32(float* c, const uint32_t* a, const uint32_t* b) {
    asm("mma.sync.aligned.m16n8k8.row.col.f32.tf32.tf32.f32 "
        "{%0,%1,%2,%3}, {%4,%5,%6,%7}, {%8,%9}, {%0,%1,%2,%3};"
        : "+f"(c[0]), "+f"(c[1]), "+f"(c[2]), "+f"(c[3])
        : "r"(a[0]), "r"(a[1]), "r"(a[2]), "r"(a[3]), "r"(b[0]), "r"(b[1]));
}
__device__ __forceinline__ void cp16(uint32_t dst_smem, const void* src, bool valid) {
    const int sz = valid ? 16 : 0;
    asm volatile("cp.async.cg.shared.global [%0], [%1], 16, %2;"
                 :: "r"(dst_smem), "l"(src), "r"(sz));
}
__device__ __forceinline__ uint32_t smem_u32(const void* p) {
    return (uint32_t)__cvta_generic_to_shared(p);
}

// ---------------------------------------------------------------------------
__global__ void zero_cnt_kernel() {
    if (threadIdx.x < NEXP) g_cnt[threadIdx.x] = 0;
}

// one block (512 threads) per token
__global__ __launch_bounds__(512)
void router_kernel(const float* __restrict__ x, const float* __restrict__ wn,
                   const float* __restrict__ Wr, const float* __restrict__ br) {
    __shared__ float WrS[DIM*NEXP];   // 32 KB
    __shared__ float s_red[16];
    __shared__ float s_pe[16*16];
    __shared__ float s_logit[16];
    __shared__ float s_rinv;

    const int n = blockIdx.x;
    const int d = threadIdx.x;
    const int wid = d >> 5, lane = d & 31;

    {
        float4* ws = (float4*)&WrS[d*16];
        const float4* wg = (const float4*)(Wr + d*16);
        ws[0] = wg[0]; ws[1] = wg[1]; ws[2] = wg[2]; ws[3] = wg[3];
    }

    const float xv = x[n*DIM + d];
    float s = xv * xv;
    #pragma unroll
    for (int o = 16; o > 0; o >>= 1) s += __shfl_down_sync(0xffffffffu, s, o);
    if (lane == 0) s_red[wid] = s;
    __syncthreads();
    if (d == 0) {
        float t = 0.f;
        #pragma unroll
        for (int w = 0; w < 16; w++) t += s_red[w];
        s_rinv = rsqrtf(t / (float)DIM + 1e-10f);
    }
    __syncthreads();

    const float xnv = wn[d] * xv * s_rinv;
    g_xn[n*DIM + d] = xnv;

    #pragma unroll
    for (int e = 0; e < NEXP; e++) {
        float p = xnv * WrS[d*16 + e];
        #pragma unroll
        for (int o = 16; o > 0; o >>= 1) p += __shfl_down_sync(0xffffffffu, p, o);
        if (lane == 0) s_pe[wid*16 + e] = p;
    }
    __syncthreads();
    if (d < NEXP) {
        float l = br[d];
        #pragma unroll
        for (int w = 0; w < 16; w++) l += s_pe[w*16 + d];
        s_logit[d] = l;
    }
    __syncthreads();

    if (d == 0) {
        int i0 = 0; float b0 = s_logit[0];
        #pragma unroll
        for (int e = 1; e < NEXP; e++) if (s_logit[e] > b0) { b0 = s_logit[e]; i0 = e; }
        int i1 = -1; float b1 = -1e30f;
        #pragma unroll
        for (int e = 0; e < NEXP; e++) {
            if (e == i0) continue;
            if (s_logit[e] > b1) { b1 = s_logit[e]; i1 = e; }
        }
        const float z  = expf(b1 - b0);
        const float w0 = 1.f / (1.f + z);
        const float w1 = z   / (1.f + z);
        const int p0 = atomicAdd(&g_cnt[i0], 1);
        const int p1 = atomicAdd(&g_cnt[i1], 1);
        g_tok[i0*NTOK + p0] = n;
        g_tok[i1*NTOK + p1] = n;
        g_gate[n*2+0] = w0;  g_gate[n*2+1] = w1;
        g_se[n*2+0]   = i0;  g_se[n*2+1]   = i1;
        g_sp[n*2+0]   = p0;  g_sp[n*2+1]   = p1;
    }
}

__global__ void offsets_kernel() {
    if (threadIdx.x == 0) {
        int s = 0;
        #pragma unroll
        for (int e = 0; e < NEXP; e++) { g_off[e] = s; s += g_cnt[e]; }
        g_off[NEXP] = s;
    }
}

// ---------------------------------------------------------------------------
// TF32 mma.sync GEMM, cp.async 2-stage pipeline, raw-fp32 operands (HW tf32
// truncation). BM=128, BN=128, BK=16, 256 threads = 8 warps (4m x 2n),
// warp tile 32x64 = 2 m16 x 8 n8 mma tiles per k8.
// Smem pads: As stride 20 (g*20+t distinct mod 32), Bs stride 136 (t*8+g).
// FIRST=1: H[off+m] = silu(gather(xn)@W1[e] + b1[e])   (K=512,  LDB=HIDD)
// FIRST=0: Y[off+m] =        H        @W2[e] + b2[e]   (K=2048, LDB=DIM)
template<int FIRST>
__global__ __launch_bounds__(256, 2)
void ffn_mma_kernel(const float* __restrict__ W, const float* __restrict__ bias) {
    const int e  = blockIdx.z;
    const int ne = g_cnt[e];
    const int m0 = blockIdx.x * 128;
    if (m0 >= ne) return;
    const int n0  = blockIdx.y * 128;
    const int off = g_off[e];
    const int tid  = threadIdx.x;
    const int lane = tid & 31, warp = tid >> 5;
    const int g = lane >> 2, t = lane & 3;
    const int wm = warp & 3, wn = warp >> 2;

    constexpr int K   = FIRST ? DIM  : HIDD;
    constexpr int LDB = FIRST ? HIDD : DIM;
    const float* Bp = W + (size_t)e * K * LDB + n0;

    __shared__ __align__(16) float As[2][128][20];   // 20.5 KB
    __shared__ __align__(16) float Bs[2][16][136];   // 17.4 KB

    // A cp.async mapping: 2 float4/thread; idx = tid + p*256 -> row idx>>2, col (idx&3)*4
    const float* arp[2];
    int arow[2], acol[2];
    #pragma unroll
    for (int p = 0; p < 2; p++) {
        const int idx = tid + p*256;
        arow[p] = idx >> 2;
        acol[p] = (idx & 3) * 4;
        const int m = m0 + arow[p];
        const float* ap = nullptr;
        if (m < ne) {
            if (FIRST) ap = g_xn + (size_t)g_tok[e*NTOK + m] * DIM;
            else       ap = g_H  + (size_t)(off + m) * HIDD;
        }
        arp[p] = ap;
    }
    // B cp.async mapping: 2 float4/thread; idx -> row idx>>5, col (idx&31)*4
    int brow[2], bcol[2];
    #pragma unroll
    for (int p = 0; p < 2; p++) {
        const int idx = tid + p*256;
        brow[p] = idx >> 5;
        bcol[p] = (idx & 31) * 4;
    }

    float acc[2][8][4];
    #pragma unroll
    for (int mt = 0; mt < 2; mt++)
        #pragma unroll
        for (int nt = 0; nt < 8; nt++)
            #pragma unroll
            for (int i = 0; i < 4; i++) acc[mt][nt][i] = 0.f;

    // ---- issue one k-tile into stage s ----
    auto issue = [&](int s, int k0) {
        #pragma unroll
        for (int p = 0; p < 2; p++) {
            const bool v = (arp[p] != nullptr);
            const float* src = v ? (arp[p] + k0 + acol[p]) : g_xn;  // dummy src when sz=0
            cp16(smem_u32(&As[s][arow[p]][acol[p]]), src, v);
        }
        #pragma unroll
        for (int p = 0; p < 2; p++) {
            cp16(smem_u32(&Bs[s][brow[p]][bcol[p]]),
                 Bp + (size_t)(k0 + brow[p]) * LDB + bcol[p], true);
        }
        asm volatile("cp.async.commit_group;");
    };

    constexpr int NT = K / 16;
    issue(0, 0);

    for (int it = 0; it < NT; it++) {
        if (it + 1 < NT) {
            issue((it + 1) & 1, (it + 1) * 16);
            asm volatile("cp.async.wait_group 1;");
        } else {
            asm volatile("cp.async.wait_group 0;");
        }
        __syncthreads();

        const int cur = it & 1;
        #pragma unroll
        for (int kk0 = 0; kk0 < 16; kk0 += 8) {
            uint32_t a[2][4];
            #pragma unroll
            for (int mt = 0; mt < 2; mt++) {
                const int row = wm*32 + mt*16 + g;
                a[mt][0] = __float_as_uint(As[cur][row  ][kk0 + t]);
                a[mt][1] = __float_as_uint(As[cur][row+8][kk0 + t]);
                a[mt][2] = __float_as_uint(As[cur][row  ][kk0 + t + 4]);
                a[mt][3] = __float_as_uint(As[cur][row+8][kk0 + t + 4]);
            }
            uint32_t b[8][2];
            #pragma unroll
            for (int nt = 0; nt < 8; nt++) {
                const int col = wn*64 + nt*8 + g;
                b[nt][0] = __float_as_uint(Bs[cur][kk0 + t    ][col]);
                b[nt][1] = __float_as_uint(Bs[cur][kk0 + t + 4][col]);
            }
            #pragma unroll
            for (int mt = 0; mt < 2; mt++)
                #pragma unroll
                for (int nt = 0; nt < 8; nt++)
                    mma_tf32(acc[mt][nt], a[mt], b[nt]);
        }
        __syncthreads();
    }

    // ---- epilogue: bias (+silu), write ----
    const float* bpr = bias + (size_t)e * LDB + n0;
    #pragma unroll
    for (int mt = 0; mt < 2; mt++) {
        #pragma unroll
        for (int r = 0; r < 2; r++) {
            const int m = m0 + wm*32 + mt*16 + g + r*8;
            if (m >= ne) continue;
            float* orow = (FIRST ? g_H + (size_t)(off + m) * HIDD
                                 : g_Y + (size_t)(off + m) * DIM) + n0;
            #pragma unroll
            for (int nt = 0; nt < 8; nt++) {
                const int lc = wn*64 + nt*8 + 2*t;
                float v0 = acc[mt][nt][r*2+0] + bpr[lc];
                float v1 = acc[mt][nt][r*2+1] + bpr[lc+1];
                if (FIRST) {
                    v0 = v0 / (1.f + expf(-v0));   // silu
                    v1 = v1 / (1.f + expf(-v1));
                }
                *(float2*)(orow + lc) = make_float2(v0, v1);
            }
        }
    }
}

// out = x + g0*Y[row0] + g1*Y[row1]   (fixed k order -> deterministic)
__global__ void combine_kernel(const float* __restrict__ x, float* __restrict__ out) {
    const int idx = blockIdx.x * blockDim.x + threadIdx.x;
    if (idx >= NTOK*DIM) return;
    const int n = idx / DIM, d = idx % DIM;
    const int r0 = g_off[g_se[n*2+0]] + g_sp[n*2+0];
    const int r1 = g_off[g_se[n*2+1]] + g_sp[n*2+1];
    out[idx] = x[idx]
             + g_gate[n*2+0] * g_Y[(size_t)r0*DIM + d]
             + g_gate[n*2+1] * g_Y[(size_t)r1*DIM + d];
}

// ---------------------------------------------------------------------------
extern "C" void kernel_launch(void* const* d_in, const int* in_sizes, int n_in,
                              void* d_out, int out_size) {
    const float* x  = (const float*)d_in[0];
    const float* wn = (const float*)d_in[1];
    const float* Wr = (const float*)d_in[2];
    const float* br = (const float*)d_in[3];
    const float* W1 = (const float*)d_in[4];
    const float* b1 = (const float*)d_in[5];
    const float* W2 = (const float*)d_in[6];
    const float* b2 = (const float*)d_in[7];
    float* out = (float*)d_out;

    zero_cnt_kernel<<<1, 32>>>();
    router_kernel<<<NTOK, 512>>>(x, wn, Wr, br);
    offsets_kernel<<<1, 32>>>();
    ffn_mma_kernel<1><<<dim3(16, HIDD/128, NEXP), 256>>>(W1, b1);
    ffn_mma_kernel<0><<<dim3(16, DIM /128, NEXP), 256>>>(W2, b2);
    combine_kernel<<<(NTOK*DIM + 255)/256, 256>>>(x, out);
}

// round 13
// speedup vs baseline: 2.6605x; 1.0286x over previous
#include <cuda_runtime.h>
#include <math.h>
#include <stdint.h>

#define NTOK 2048
#define DIM  512
#define NEXP 16
#define TOPK 2
#define HIDD 2048
#define NASSIGN (NTOK*TOPK)

// ---------------- scratch (device globals: no allocation allowed) ----------
__device__ float g_xn[NTOK*DIM];          // 4 MB  normalized activations
__device__ float g_H [NASSIGN*HIDD];      // 32 MB silu(h) per assignment row
__device__ float g_Y [NASSIGN*DIM];       // 8 MB  expert outputs per assignment row
__device__ int   g_cnt[NEXP];
__device__ int   g_off[NEXP+1];
__device__ int   g_tok[NEXP*NTOK];        // per-expert token lists
__device__ float g_gate[NTOK*TOPK];
__device__ int   g_se[NTOK*TOPK];         // expert id per (token,k)
__device__ int   g_sp[NTOK*TOPK];         // position within expert list per (token,k)

// ---- helpers --------------------------------------------------------------
__device__ __forceinline__ void mma_tf32(float* c, const uint32_t* a, const uint32_t* b) {
    asm("mma.sync.aligned.m16n8k8.row.col.f32.tf32.tf32.f32 "
        "{%0,%1,%2,%3}, {%4,%5,%6,%7}, {%8,%9}, {%0,%1,%2,%3};"
        : "+f"(c[0]), "+f"(c[1]), "+f"(c[2]), "+f"(c[3])
        : "r"(a[0]), "r"(a[1]), "r"(a[2]), "r"(a[3]), "r"(b[0]), "r"(b[1]));
}
__device__ __forceinline__ void cp16(uint32_t dst_smem, const void* src, bool valid) {
    const int sz = valid ? 16 : 0;
    asm volatile("cp.async.cg.shared.global [%0], [%1], 16, %2;"
                 :: "r"(dst_smem), "l"(src), "r"(sz));
}
__device__ __forceinline__ uint32_t smem_u32(const void* p) {
    return (uint32_t)__cvta_generic_to_shared(p);
}

// ---------------------------------------------------------------------------
__global__ void zero_cnt_kernel() {
    if (threadIdx.x < NEXP) g_cnt[threadIdx.x] = 0;
}

// one block (512 threads) per token
__global__ __launch_bounds__(512)
void router_kernel(const float* __restrict__ x, const float* __restrict__ wn,
                   const float* __restrict__ Wr, const float* __restrict__ br) {
    __shared__ float WrS[DIM*NEXP];   // 32 KB
    __shared__ float s_red[16];
    __shared__ float s_pe[16*16];
    __shared__ float s_logit[16];
    __shared__ float s_rinv;

    const int n = blockIdx.x;
    const int d = threadIdx.x;
    const int wid = d >> 5, lane = d & 31;

    {
        float4* ws = (float4*)&WrS[d*16];
        const float4* wg = (const float4*)(Wr + d*16);
        ws[0] = wg[0]; ws[1] = wg[1]; ws[2] = wg[2]; ws[3] = wg[3];
    }

    const float xv = x[n*DIM + d];
    float s = xv * xv;
    #pragma unroll
    for (int o = 16; o > 0; o >>= 1) s += __shfl_down_sync(0xffffffffu, s, o);
    if (lane == 0) s_red[wid] = s;
    __syncthreads();
    if (d == 0) {
        float t = 0.f;
        #pragma unroll
        for (int w = 0; w < 16; w++) t += s_red[w];
        s_rinv = rsqrtf(t / (float)DIM + 1e-10f);
    }
    __syncthreads();

    const float xnv = wn[d] * xv * s_rinv;
    g_xn[n*DIM + d] = xnv;

    #pragma unroll
    for (int e = 0; e < NEXP; e++) {
        float p = xnv * WrS[d*16 + e];
        #pragma unroll
        for (int o = 16; o > 0; o >>= 1) p += __shfl_down_sync(0xffffffffu, p, o);
        if (lane == 0) s_pe[wid*16 + e] = p;
    }
    __syncthreads();
    if (d < NEXP) {
        float l = br[d];
        #pragma unroll
        for (int w = 0; w < 16; w++) l += s_pe[w*16 + d];
        s_logit[d] = l;
    }
    __syncthreads();

    if (d == 0) {
        int i0 = 0; float b0 = s_logit[0];
        #pragma unroll
        for (int e = 1; e < NEXP; e++) if (s_logit[e] > b0) { b0 = s_logit[e]; i0 = e; }
        int i1 = -1; float b1 = -1e30f;
        #pragma unroll
        for (int e = 0; e < NEXP; e++) {
            if (e == i0) continue;
            if (s_logit[e] > b1) { b1 = s_logit[e]; i1 = e; }
        }
        const float z  = expf(b1 - b0);
        const float w0 = 1.f / (1.f + z);
        const float w1 = z   / (1.f + z);
        const int p0 = atomicAdd(&g_cnt[i0], 1);
        const int p1 = atomicAdd(&g_cnt[i1], 1);
        g_tok[i0*NTOK + p0] = n;
        g_tok[i1*NTOK + p1] = n;
        g_gate[n*2+0] = w0;  g_gate[n*2+1] = w1;
        g_se[n*2+0]   = i0;  g_se[n*2+1]   = i1;
        g_sp[n*2+0]   = p0;  g_sp[n*2+1]   = p1;
    }
}

__global__ void offsets_kernel() {
    if (threadIdx.x == 0) {
        int s = 0;
        #pragma unroll
        for (int e = 0; e < NEXP; e++) { g_off[e] = s; s += g_cnt[e]; }
        g_off[NEXP] = s;
    }
}

// ---------------------------------------------------------------------------
// TF32 mma.sync GEMM, 3-stage cp.async pipeline, ONE barrier per k-tile.
// BM=128, BN=128, BK=16, 256 threads = 8 warps (4m x 2n), warp tile 32x64.
// Dynamic smem: 3 stages of As[128][20] + Bs[16][136]  (56832 B).
// Loop order: wait_group -> syncthreads -> issue(it+2) -> compute(it).
//   Barrier at iter it proves all warps finished compute(it-1), so writing
//   stage (it+2)%3 == (it-1)%3 after it is race-free; wait_group 1 leaves only
//   tile it+1 in flight -> tile it resident, copies get ~2 compute phases.
// FIRST=1: H[off+m] = silu(gather(xn)@W1[e] + b1[e])   (K=512,  LDB=HIDD)
// FIRST=0: Y[off+m] =        H        @W2[e] + b2[e]   (K=2048, LDB=DIM)
template<int FIRST>
__global__ __launch_bounds__(256, 2)
void ffn_mma_kernel(const float* __restrict__ W, const float* __restrict__ bias) {
    const int e  = blockIdx.z;
    const int ne = g_cnt[e];
    const int m0 = blockIdx.x * 128;
    if (m0 >= ne) return;
    const int n0  = blockIdx.y * 128;
    const int off = g_off[e];
    const int tid  = threadIdx.x;
    const int lane = tid & 31, warp = tid >> 5;
    const int g = lane >> 2, t = lane & 3;
    const int wm = warp & 3, wn = warp >> 2;

    constexpr int K   = FIRST ? DIM  : HIDD;
    constexpr int LDB = FIRST ? HIDD : DIM;
    const float* Bp = W + (size_t)e * K * LDB + n0;

    // dynamic smem: 3 x As[128][20], then 3 x Bs[16][136]
    extern __shared__ __align__(16) float smem[];
    float (*As)[128][20]  = (float (*)[128][20])smem;
    float (*Bs)[16][136]  = (float (*)[16][136])(smem + 3*128*20);

    // A cp.async mapping: 2 float4/thread; idx = tid + p*256 -> row idx>>2, col (idx&3)*4
    const float* arp[2];
    int arow[2], acol[2];
    #pragma unroll
    for (int p = 0; p < 2; p++) {
        const int idx = tid + p*256;
        arow[p] = idx >> 2;
        acol[p] = (idx & 3) * 4;
        const int m = m0 + arow[p];
        const float* ap = nullptr;
        if (m < ne) {
            if (FIRST) ap = g_xn + (size_t)g_tok[e*NTOK + m] * DIM;
            else       ap = g_H  + (size_t)(off + m) * HIDD;
        }
        arp[p] = ap;
    }
    // B cp.async mapping: 2 float4/thread; idx -> row idx>>5, col (idx&31)*4
    int brow[2], bcol[2];
    #pragma unroll
    for (int p = 0; p < 2; p++) {
        const int idx = tid + p*256;
        brow[p] = idx >> 5;
        bcol[p] = (idx & 31) * 4;
    }

    float acc[2][8][4];
    #pragma unroll
    for (int mt = 0; mt < 2; mt++)
        #pragma unroll
        for (int nt = 0; nt < 8; nt++)
            #pragma unroll
            for (int i = 0; i < 4; i++) acc[mt][nt][i] = 0.f;

    auto issue = [&](int s, int k0) {
        #pragma unroll
        for (int p = 0; p < 2; p++) {
            const bool v = (arp[p] != nullptr);
            const float* src = v ? (arp[p] + k0 + acol[p]) : g_xn;  // dummy src when sz=0
            cp16(smem_u32(&As[s][arow[p]][acol[p]]), src, v);
        }
        #pragma unroll
        for (int p = 0; p < 2; p++) {
            cp16(smem_u32(&Bs[s][brow[p]][bcol[p]]),
                 Bp + (size_t)(k0 + brow[p]) * LDB + bcol[p], true);
        }
        asm volatile("cp.async.commit_group;");
    };

    constexpr int NT = K / 16;
    issue(0, 0);
    issue(1, 16);

    int cur = 0;                      // it % 3
    for (int it = 0; it < NT; it++) {
        if (it < NT - 1) asm volatile("cp.async.wait_group 1;");
        else             asm volatile("cp.async.wait_group 0;");
        __syncthreads();

        if (it + 2 < NT) {
            int s2 = cur + 2; if (s2 >= 3) s2 -= 3;
            issue(s2, (it + 2) * 16);
        }

        #pragma unroll
        for (int kk0 = 0; kk0 < 16; kk0 += 8) {
            uint32_t a[2][4];
            #pragma unroll
            for (int mt = 0; mt < 2; mt++) {
                const int row = wm*32 + mt*16 + g;
                a[mt][0] = __float_as_uint(As[cur][row  ][kk0 + t]);
                a[mt][1] = __float_as_uint(As[cur][row+8][kk0 + t]);
                a[mt][2] = __float_as_uint(As[cur][row  ][kk0 + t + 4]);
                a[mt][3] = __float_as_uint(As[cur][row+8][kk0 + t + 4]);
            }
            uint32_t b[8][2];
            #pragma unroll
            for (int nt = 0; nt < 8; nt++) {
                const int col = wn*64 + nt*8 + g;
                b[nt][0] = __float_as_uint(Bs[cur][kk0 + t    ][col]);
                b[nt][1] = __float_as_uint(Bs[cur][kk0 + t + 4][col]);
            }
            #pragma unroll
            for (int mt = 0; mt < 2; mt++)
                #pragma unroll
                for (int nt = 0; nt < 8; nt++)
                    mma_tf32(acc[mt][nt], a[mt], b[nt]);
        }

        if (++cur == 3) cur = 0;
    }

    // ---- epilogue: bias (+silu), write ----
    const float* bpr = bias + (size_t)e * LDB + n0;
    #pragma unroll
    for (int mt = 0; mt < 2; mt++) {
        #pragma unroll
        for (int r = 0; r < 2; r++) {
            const int m = m0 + wm*32 + mt*16 + g + r*8;
            if (m >= ne) continue;
            float* orow = (FIRST ? g_H + (size_t)(off + m) * HIDD
                                 : g_Y + (size_t)(off + m) * DIM) + n0;
            #pragma unroll
            for (int nt = 0; nt < 8; nt++) {
                const int lc = wn*64 + nt*8 + 2*t;
                float v0 = acc[mt][nt][r*2+0] + bpr[lc];
                float v1 = acc[mt][nt][r*2+1] + bpr[lc+1];
                if (FIRST) {
                    v0 = v0 / (1.f + expf(-v0));   // silu
                    v1 = v1 / (1.f + expf(-v1));
                }
                *(float2*)(orow + lc) = make_float2(v0, v1);
            }
        }
    }
}

// out = x + g0*Y[row0] + g1*Y[row1]   (fixed k order -> deterministic)
__global__ void combine_kernel(const float* __restrict__ x, float* __restrict__ out) {
    const int idx = blockIdx.x * blockDim.x + threadIdx.x;
    if (idx >= NTOK*DIM) return;
    const int n = idx / DIM, d = idx % DIM;
    const int r0 = g_off[g_se[n*2+0]] + g_sp[n*2+0];
    const int r1 = g_off[g_se[n*2+1]] + g_sp[n*2+1];
    out[idx] = x[idx]
             + g_gate[n*2+0] * g_Y[(size_t)r0*DIM + d]
             + g_gate[n*2+1] * g_Y[(size_t)r1*DIM + d];
}

// ---------------------------------------------------------------------------
extern "C" void kernel_launch(void* const* d_in, const int* in_sizes, int n_in,
                              void* d_out, int out_size) {
    const float* x  = (const float*)d_in[0];
    const float* wn = (const float*)d_in[1];
    const float* Wr = (const float*)d_in[2];
    const float* br = (const float*)d_in[3];
    const float* W1 = (const float*)d_in[4];
    const float* b1 = (const float*)d_in[5];
    const float* W2 = (const float*)d_in[6];
    const float* b2 = (const float*)d_in[7];
    float* out = (float*)d_out;

    const int SMEM = (3*128*20 + 3*16*136) * 4;   // 56832 B
    // unconditional (idempotent, deterministic — no static guards allowed)
    cudaFuncSetAttribute(ffn_mma_kernel<1>,
                         cudaFuncAttributeMaxDynamicSharedMemorySize, SMEM);
    cudaFuncSetAttribute(ffn_mma_kernel<0>,
                         cudaFuncAttributeMaxDynamicSharedMemorySize, SMEM);

    zero_cnt_kernel<<<1, 32>>>();
    router_kernel<<<NTOK, 512>>>(x, wn, Wr, br);
    offsets_kernel<<<1, 32>>>();
    ffn_mma_kernel<1><<<dim3(16, HIDD/128, NEXP), 256, SMEM>>>(W1, b1);
    ffn_mma_kernel<0><<<dim3(16, DIM /128, NEXP), 256, SMEM>>>(W2, b2);
    combine_kernel<<<(NTOK*DIM + 255)/256, 256>>>(x, out);
}